// round 17
// baseline (speedup 1.0000x reference)
#include <cuda_runtime.h>
#include <cuda_fp16.h>
#include <math.h>
#include <stdint.h>

#define N_POI 50000
#define DIM 128
#define E_EDGES 400000
#define GCN_NUM 3
#define BATCH 64
#define LSEQ 100
#define NTOK (BATCH*LSEQ)
#define DIRE (2*E_EDGES)
#define SCB 256
#define NSCB ((N_POI + SCB - 1)/SCB)   // 196

// ---------------- device scratch ----------------
__device__ __align__(16) int    g_cnt[N_POI];
__device__ __align__(16) int    g_part[NSCB];
__device__ __align__(16) int    g_rowptr[N_POI+1];
__device__ __align__(16) int    g_rowcur[N_POI];
__device__ __align__(16) float  g_dis[N_POI];
__device__ __align__(16) int2   g_edge[DIRE];          // packed (col, weight-bits)
__device__ __align__(16) float  g_bufA[N_POI*DIM];
__device__ __align__(16) __half g_tmpH[N_POI*DIM];
__device__ __align__(16) __half g_encH[N_POI*DIM];
__device__ __align__(16) float  g_qkv[NTOK*3*DIM];
__device__ __align__(16) float  g_o[NTOK*DIM];

// fp16 HMMA m16n8k16, fp32 accumulate
__device__ __forceinline__ void mma_f16(float* d, const uint32_t* a, const uint32_t* b){
    asm volatile("mma.sync.aligned.m16n8k16.row.col.f32.f16.f16.f32 "
        "{%0,%1,%2,%3}, {%4,%5,%6,%7}, {%8,%9}, {%0,%1,%2,%3};"
        : "+f"(d[0]), "+f"(d[1]), "+f"(d[2]), "+f"(d[3])
        : "r"(a[0]), "r"(a[1]), "r"(a[2]), "r"(a[3]), "r"(b[0]), "r"(b[1]));
}
__device__ __forceinline__ uint2 cvt_f4_h4(float4 v){
    uint2 h;
    *(__half2*)&h.x = __floats2half2_rn(v.x, v.y);
    *(__half2*)&h.y = __floats2half2_rn(v.z, v.w);
    return h;
}

// ---------------- #1: histogram ----------------
__global__ void k_hist(const int* __restrict__ e0, const int* __restrict__ e1, int* cnt){
    int e = blockIdx.x*256 + threadIdx.x;
    if (e < E_EDGES){
        atomicAdd(&cnt[e0[e]], 1);
        atomicAdd(&cnt[e1[e]], 1);
    }
}

// ---------------- scanA ----------------
__global__ void k_scanA(const int* __restrict__ cnt, int* __restrict__ part){
    __shared__ int ws[8];
    int idx = blockIdx.x*SCB + threadIdx.x;
    int v = (idx < N_POI) ? cnt[idx] : 0;
    int s = v;
    #pragma unroll
    for (int o = 16; o > 0; o >>= 1) s += __shfl_xor_sync(0xffffffffu, s, o);
    int lane = threadIdx.x & 31, warp = threadIdx.x >> 5;
    if (lane == 0) ws[warp] = s;
    __syncthreads();
    if (threadIdx.x == 0){
        int t = 0;
        #pragma unroll
        for (int w = 0; w < 8; w++) t += ws[w];
        part[blockIdx.x] = t;
    }
}

// ---------------- scanB ----------------
__global__ void k_scanB(const int* __restrict__ cnt, const int* __restrict__ part,
                        int* __restrict__ rowptr, int* __restrict__ rowcur,
                        float* __restrict__ dis){
    __shared__ int sp[256];
    __shared__ int wsum[8];
    int t = threadIdx.x;
    int b = blockIdx.x;

    sp[t] = (t < NSCB) ? part[t] : 0;
    __syncthreads();
    #pragma unroll
    for (int o = 1; o < 256; o <<= 1){
        int v = (t >= o) ? sp[t - o] : 0;
        __syncthreads();
        sp[t] += v;
        __syncthreads();
    }
    int base = (b == 0) ? 0 : sp[b - 1];
    int total = sp[NSCB - 1];

    int idx = b*SCB + t;
    int v = (idx < N_POI) ? cnt[idx] : 0;
    int inc = v;
    int lane = t & 31, warp = t >> 5;
    #pragma unroll
    for (int o = 1; o < 32; o <<= 1){
        int x = __shfl_up_sync(0xffffffffu, inc, o);
        if (lane >= o) inc += x;
    }
    if (lane == 31) wsum[warp] = inc;
    __syncthreads();
    if (t < 8){
        int acc = 0;
        #pragma unroll
        for (int w = 0; w < 8; w++){
            int y = (w < t) ? wsum[w] : 0;
            acc += y;
        }
        __syncwarp(0xffu);
        wsum[t] = acc;
    }
    __syncthreads();
    int excl = inc - v + wsum[warp];
    if (idx < N_POI){
        int rp = base + excl;
        rowptr[idx] = rp;
        rowcur[idx] = rp;
        dis[idx] = rsqrtf((float)(v + 1));
    }
    if (b == 0 && t == 0) rowptr[N_POI] = total;
}

// ---------------- scatter: packed int2 edge records ----------------
__global__ void k_scatter(const int* __restrict__ e0, const int* __restrict__ e1,
                          const float* __restrict__ dv, const float* __restrict__ dis,
                          int* rowcur, int2* __restrict__ edge){
    int e = blockIdx.x*256 + threadIdx.x;
    if (e >= E_EDGES) return;
    int a = e0[e], b = e1[e];
    float d = dv[e];
    float wv = __expf(-d*d) * dis[a] * dis[b];
    int wbits = __float_as_int(wv);
    int p = atomicAdd(&rowcur[a], 1);
    edge[p] = make_int2(b, wbits);
    p = atomicAdd(&rowcur[b], 1);
    edge[p] = make_int2(a, wbits);
}

// ---------------- fp16 HMMA GEMM (A fp32 or fp16; W fp32 cvt in staging) ----------------
#define PH 136
__global__ void __launch_bounds__(512, 2)
k_gemm_p(const void* __restrict__ Xin, const float4* __restrict__ Wf4,
         uint32_t* __restrict__ tmpH, int M, int a_fp32){
    extern __shared__ __half shh[];
    __half* As = shh;
    __half* Bs = shh + 128*PH;
    int tid = threadIdx.x;
    int row0 = blockIdx.x * 128;

    if (a_fp32){
        const float4* X4 = (const float4*)Xin;
        #pragma unroll
        for (int it = 0; it < 8; it++){
            int i = tid + it*512;
            int r = i >> 5, c4 = i & 31;
            int grow = row0 + r;
            float4 v = (grow < M) ? X4[grow*32 + c4] : make_float4(0.f,0.f,0.f,0.f);
            *(uint2*)&As[r*PH + c4*4] = cvt_f4_h4(v);
            *(uint2*)&Bs[r*PH + c4*4] = cvt_f4_h4(Wf4[i]);
        }
    } else {
        const uint2* Xh2 = (const uint2*)Xin;
        #pragma unroll
        for (int it = 0; it < 8; it++){
            int i = tid + it*512;
            int r = i >> 5, c4 = i & 31;
            int grow = row0 + r;
            uint2 av = (grow < M) ? Xh2[grow*32 + c4] : make_uint2(0u, 0u);
            *(uint2*)&As[r*PH + c4*4] = av;
            *(uint2*)&Bs[r*PH + c4*4] = cvt_f4_h4(Wf4[i]);
        }
    }
    __syncthreads();

    int wid = tid >> 5, lane = tid & 31;
    int m_base = (wid & 3)*32, n_base = (wid >> 2)*32;
    int qr = lane >> 2, qc = lane & 3;

    float acc[2][4][4];
    #pragma unroll
    for (int mi = 0; mi < 2; mi++)
        #pragma unroll
        for (int ni = 0; ni < 4; ni++)
            #pragma unroll
            for (int j = 0; j < 4; j++) acc[mi][ni][j] = 0.f;

    #pragma unroll
    for (int k0 = 0; k0 < 128; k0 += 16){
        uint32_t a[2][4];
        #pragma unroll
        for (int mi = 0; mi < 2; mi++){
            const __half* ap = As + (m_base + mi*16 + qr)*PH + k0 + 2*qc;
            a[mi][0] = *(const uint32_t*)ap;
            a[mi][1] = *(const uint32_t*)(ap + 8*PH);
            a[mi][2] = *(const uint32_t*)(ap + 8);
            a[mi][3] = *(const uint32_t*)(ap + 8*PH + 8);
        }
        uint32_t b[4][2];
        #pragma unroll
        for (int ni = 0; ni < 4; ni++){
            const __half* bp = Bs + (n_base + ni*8 + qr)*PH + k0 + 2*qc;
            b[ni][0] = *(const uint32_t*)bp;
            b[ni][1] = *(const uint32_t*)(bp + 8);
        }
        #pragma unroll
        for (int mi = 0; mi < 2; mi++)
            #pragma unroll
            for (int ni = 0; ni < 4; ni++)
                mma_f16(acc[mi][ni], a[mi], b[ni]);
    }

    #pragma unroll
    for (int mi = 0; mi < 2; mi++){
        int r0 = row0 + m_base + mi*16 + qr;
        int r1 = r0 + 8;
        #pragma unroll
        for (int ni = 0; ni < 4; ni++){
            float* d = acc[mi][ni];
            int col = n_base + ni*8 + qc*2;
            if (r0 < M){
                __half2 h = __floats2half2_rn(d[0], d[1]);
                tmpH[r0*64 + (col >> 1)] = *(uint32_t*)&h;
            }
            if (r1 < M){
                __half2 h = __floats2half2_rn(d[2], d[3]);
                tmpH[r1*64 + (col >> 1)] = *(uint32_t*)&h;
            }
        }
    }
}

// ---------------- SpMM (uint2 gather, packed edges) + fused epilogue ----------------
__global__ void k_spmm_f(const uint2* __restrict__ tmpH2, const int* __restrict__ rowptr,
                         const int2* __restrict__ edge, const float* __restrict__ dis,
                         const float4* __restrict__ bias4,
                         uint2* __restrict__ encH2, float4* __restrict__ outF4,
                         int writeF){
    int row = blockIdx.x*8 + (threadIdx.x >> 5);
    int lane = threadIdx.x & 31;
    if (row >= N_POI) return;
    float ds = dis[row];
    float sl = ds*ds;

    uint2 xs = tmpH2[row*32 + lane];
    float2 xa = __half22float2(*(const __half2*)&xs.x);
    float2 xb = __half22float2(*(const __half2*)&xs.y);
    float4 acc = make_float4(sl*xa.x, sl*xa.y, sl*xb.x, sl*xb.y);

    int s = __ldg(&rowptr[row]), e = __ldg(&rowptr[row+1]);
    int i = s;
    for (; i + 8 <= e; i += 8){
        int2 ed[8];
        #pragma unroll
        for (int j = 0; j < 8; j++) ed[j] = __ldg(&edge[i + j]);
        #pragma unroll
        for (int j = 0; j < 8; j++){
            float w = __int_as_float(ed[j].y);
            uint2 u = tmpH2[ed[j].x*32 + lane];
            float2 a = __half22float2(*(const __half2*)&u.x);
            float2 b = __half22float2(*(const __half2*)&u.y);
            acc.x = fmaf(w, a.x, acc.x);
            acc.y = fmaf(w, a.y, acc.y);
            acc.z = fmaf(w, b.x, acc.z);
            acc.w = fmaf(w, b.y, acc.w);
        }
    }
    for (; i < e; i++){
        int2 ed = __ldg(&edge[i]);
        float w = __int_as_float(ed.y);
        uint2 u = tmpH2[ed.x*32 + lane];
        float2 a = __half22float2(*(const __half2*)&u.x);
        float2 b = __half22float2(*(const __half2*)&u.y);
        acc.x = fmaf(w, a.x, acc.x);
        acc.y = fmaf(w, a.y, acc.y);
        acc.z = fmaf(w, b.x, acc.z);
        acc.w = fmaf(w, b.y, acc.w);
    }

    float4 b = bias4[lane];
    float v0 = acc.x + b.x, v1 = acc.y + b.y, v2 = acc.z + b.z, v3 = acc.w + b.w;
    v0 = (v0 >= 0.f) ? v0 : 0.01f*v0;
    v1 = (v1 >= 0.f) ? v1 : 0.01f*v1;
    v2 = (v2 >= 0.f) ? v2 : 0.01f*v2;
    v3 = (v3 >= 0.f) ? v3 : 0.01f*v3;
    float ss = fmaf(v0,v0, fmaf(v1,v1, fmaf(v2,v2, v3*v3)));
    #pragma unroll
    for (int o = 16; o > 0; o >>= 1) ss += __shfl_xor_sync(0xffffffffu, ss, o);
    float inv = 1.0f / fmaxf(sqrtf(ss), 1e-12f);
    float y0 = v0*inv, y1 = v1*inv, y2 = v2*inv, y3 = v3*inv;
    uint2 oh;
    *(__half2*)&oh.x = __floats2half2_rn(y0, y1);
    *(__half2*)&oh.y = __floats2half2_rn(y2, y3);
    encH2[row*32 + lane] = oh;
    if (writeF) outF4[row*32 + lane] = make_float4(y0, y1, y2, y3);
}

// ---------------- QKV via fp16 HMMA (gathered rows; W fp32 cvt in staging) ----------------
__global__ void __launch_bounds__(512, 2)
k_qkv_h(const uint2* __restrict__ encH2, const int* __restrict__ xidx,
        const float4* __restrict__ inw4, const float* __restrict__ inb,
        float* __restrict__ qkv){
    extern __shared__ __half shh[];
    __half* As = shh;
    __half* Bs = shh + 128*PH;
    int tid = threadIdx.x;
    int row0 = blockIdx.x * 128;
    int nb = blockIdx.y;

    const float4* W4 = inw4 + nb*DIM*32;
    #pragma unroll
    for (int it = 0; it < 8; it++){
        int i = tid + it*512;
        int r = i >> 5, c4 = i & 31;
        int src = __ldg(&xidx[row0 + r]);
        *(uint2*)&As[r*PH + c4*4] = encH2[src*32 + c4];
        *(uint2*)&Bs[r*PH + c4*4] = cvt_f4_h4(W4[i]);
    }
    __syncthreads();

    int wid = tid >> 5, lane = tid & 31;
    int m_base = (wid & 3)*32, n_base = (wid >> 2)*32;
    int qr = lane >> 2, qc = lane & 3;

    float acc[2][4][4];
    #pragma unroll
    for (int mi = 0; mi < 2; mi++)
        #pragma unroll
        for (int ni = 0; ni < 4; ni++)
            #pragma unroll
            for (int j = 0; j < 4; j++) acc[mi][ni][j] = 0.f;

    #pragma unroll
    for (int k0 = 0; k0 < 128; k0 += 16){
        uint32_t a[2][4];
        #pragma unroll
        for (int mi = 0; mi < 2; mi++){
            const __half* ap = As + (m_base + mi*16 + qr)*PH + k0 + 2*qc;
            a[mi][0] = *(const uint32_t*)ap;
            a[mi][1] = *(const uint32_t*)(ap + 8*PH);
            a[mi][2] = *(const uint32_t*)(ap + 8);
            a[mi][3] = *(const uint32_t*)(ap + 8*PH + 8);
        }
        uint32_t b[4][2];
        #pragma unroll
        for (int ni = 0; ni < 4; ni++){
            const __half* bp = Bs + (n_base + ni*8 + qr)*PH + k0 + 2*qc;
            b[ni][0] = *(const uint32_t*)bp;
            b[ni][1] = *(const uint32_t*)(bp + 8);
        }
        #pragma unroll
        for (int mi = 0; mi < 2; mi++)
            #pragma unroll
            for (int ni = 0; ni < 4; ni++)
                mma_f16(acc[mi][ni], a[mi], b[ni]);
    }

    #pragma unroll
    for (int mi = 0; mi < 2; mi++){
        int r0 = row0 + m_base + mi*16 + qr;
        int r1 = r0 + 8;
        #pragma unroll
        for (int ni = 0; ni < 4; ni++){
            float* d = acc[mi][ni];
            int col = n_base + ni*8 + qc*2;
            float2 bj = *(const float2*)&inb[nb*DIM + col];
            *(float2*)&qkv[r0*(3*DIM) + nb*DIM + col] = make_float2(d[0]+bj.x, d[1]+bj.y);
            *(float2*)&qkv[r1*(3*DIM) + nb*DIM + col] = make_float2(d[2]+bj.x, d[3]+bj.y);
        }
    }
}

// ---------------- attention ----------------
__global__ void k_attn(const float* __restrict__ qkv, float* __restrict__ o){
    extern __shared__ float sha[];
    float* sq  = sha;
    float* skT = sha + LSEQ*16;
    float* sv  = sha + 2*LSEQ*16;
    float* sp  = sha + 3*LSEQ*16;
    int b = blockIdx.x, h = blockIdx.y;
    int tid = threadIdx.x;
    for (int idx = tid; idx < LSEQ*16; idx += 128){
        int t = idx >> 4, d = idx & 15;
        int base = (b*LSEQ + t)*(3*DIM) + h*16 + d;
        sq[idx] = qkv[base];
        sv[idx] = qkv[base + 2*DIM];
    }
    for (int idx = tid; idx < LSEQ*16; idx += 128){
        int d = idx / LSEQ, t = idx - d*LSEQ;
        skT[idx] = qkv[(b*LSEQ + t)*(3*DIM) + DIM + h*16 + d];
    }
    __syncthreads();

    int lane = tid & 31, warp = tid >> 5;
    for (int qi = warp; qi < LSEQ; qi += 4){
        float q[16];
        #pragma unroll
        for (int d = 0; d < 16; d++) q[d] = sq[qi*16 + d];
        float v[4];
        float m = -1e30f;
        #pragma unroll
        for (int g = 0; g < 4; g++){
            int j = lane + g*32;
            float s = -1e30f;
            if (j < LSEQ){
                s = 0.f;
                #pragma unroll
                for (int d = 0; d < 16; d++) s = fmaf(q[d], skT[d*LSEQ + j], s);
                s *= 0.25f;
            }
            v[g] = s;
            m = fmaxf(m, s);
        }
        #pragma unroll
        for (int t = 16; t > 0; t >>= 1) m = fmaxf(m, __shfl_xor_sync(0xffffffffu, m, t));
        float ssum = 0.f;
        #pragma unroll
        for (int g = 0; g < 4; g++){
            int j = lane + g*32;
            float p = (j < LSEQ) ? __expf(v[g] - m) : 0.f;
            v[g] = p;
            ssum += p;
        }
        #pragma unroll
        for (int t = 16; t > 0; t >>= 1) ssum += __shfl_xor_sync(0xffffffffu, ssum, t);
        float inv = 1.0f / ssum;
        #pragma unroll
        for (int g = 0; g < 4; g++){
            int j = lane + g*32;
            if (j < LSEQ) sp[qi*LSEQ + j] = v[g]*inv;
        }
    }
    __syncthreads();

    const float4* sv4 = (const float4*)sv;
    for (int u = tid; u < LSEQ*4; u += 128){
        int qi = u >> 2, dg = u & 3;
        float4 acc = make_float4(0.f,0.f,0.f,0.f);
        const float* pp = sp + qi*LSEQ;
        #pragma unroll 4
        for (int j = 0; j < LSEQ; j++){
            float p = pp[j];
            float4 vv = sv4[j*4 + dg];
            acc.x = fmaf(p, vv.x, acc.x);
            acc.y = fmaf(p, vv.y, acc.y);
            acc.z = fmaf(p, vv.z, acc.z);
            acc.w = fmaf(p, vv.w, acc.w);
        }
        *(float4*)&o[(b*LSEQ + qi)*DIM + h*16 + dg*4] = acc;
    }
}

// ---------------- tail ----------------
__global__ void k_tail(const float* __restrict__ o, const float* __restrict__ ow,
                       const float* __restrict__ ob, const float* __restrict__ enc,
                       const int* __restrict__ pidx, float* __restrict__ out){
    __shared__ float sx[DIM];
    int b = blockIdx.x, j = threadIdx.x;
    float s = 0.0f;
    for (int i = 0; i < LSEQ; i++) s += o[(b*LSEQ + i)*DIM + j];
    sx[j] = s * (1.0f/LSEQ);
    __syncthreads();
    float acc = ob[j];
    #pragma unroll 4
    for (int k = 0; k < DIM; k++) acc += sx[k]*ow[j*DIM + k];
    out[b*DIM + j] = acc;
    out[BATCH*DIM + b*DIM + j] = enc[pidx[b]*DIM + j];
}

// ---------------- host launch ----------------
extern "C" void kernel_launch(void* const* d_in, const int* in_sizes, int n_in,
                              void* d_out, int out_size){
    const float* embeds = (const float*)d_in[0];
    const float* gcnW   = (const float*)d_in[1];
    const float* gcnb   = (const float*)d_in[2];
    const float* inw    = (const float*)d_in[3];
    const float* inb    = (const float*)d_in[4];
    const float* ow     = (const float*)d_in[5];
    const float* ob     = (const float*)d_in[6];
    const float* dv     = (const float*)d_in[7];
    const int*   edges  = (const int*)d_in[8];
    const int*   xidx   = (const int*)d_in[9];
    const int*   pidx   = (const int*)d_in[10];
    const int* e0 = edges;
    const int* e1 = edges + E_EDGES;
    float* out = (float*)d_out;

    int *cnt, *part, *rowptr, *rowcur;
    int2* edge;
    float *dis, *bA, *qkv, *obuf;
    __half *encH, *tmpH;
    cudaGetSymbolAddress((void**)&cnt,    g_cnt);
    cudaGetSymbolAddress((void**)&part,   g_part);
    cudaGetSymbolAddress((void**)&rowptr, g_rowptr);
    cudaGetSymbolAddress((void**)&rowcur, g_rowcur);
    cudaGetSymbolAddress((void**)&dis,    g_dis);
    cudaGetSymbolAddress((void**)&edge,   g_edge);
    cudaGetSymbolAddress((void**)&bA,     g_bufA);
    cudaGetSymbolAddress((void**)&tmpH,   g_tmpH);
    cudaGetSymbolAddress((void**)&encH,   g_encH);
    cudaGetSymbolAddress((void**)&qkv,    g_qkv);
    cudaGetSymbolAddress((void**)&obuf,   g_o);

    const int smem_gemm = 2*128*PH*(int)sizeof(__half);
    const int smem_attn = (3*LSEQ*16 + LSEQ*LSEQ)*(int)sizeof(float);
    cudaFuncSetAttribute(k_gemm_p, cudaFuncAttributeMaxDynamicSharedMemorySize, smem_gemm);
    cudaFuncSetAttribute(k_qkv_h,  cudaFuncAttributeMaxDynamicSharedMemorySize, smem_gemm);
    cudaFuncSetAttribute(k_attn,   cudaFuncAttributeMaxDynamicSharedMemorySize, smem_attn);

    cudaMemsetAsync(cnt, 0, N_POI*sizeof(int));
    k_hist<<<(E_EDGES+255)/256, 256>>>(e0, e1, cnt);
    // layer-1 GEMM straight from fp32 embeds (independent of CSR build)
    k_gemm_p<<<(N_POI+127)/128, 512, smem_gemm>>>(
        (const void*)embeds, (const float4*)gcnW, (uint32_t*)tmpH, N_POI, 1);
    k_scanA<<<NSCB, SCB>>>(cnt, part);
    k_scanB<<<NSCB, SCB>>>(cnt, part, rowptr, rowcur, dis);
    k_scatter<<<(E_EDGES+255)/256, 256>>>(e0, e1, dv, dis, rowcur, edge);
    k_spmm_f<<<(N_POI+7)/8, 256>>>((const uint2*)tmpH, rowptr, edge, dis,
                                   (const float4*)(gcnb + 0*DIM),
                                   (uint2*)encH, (float4*)bA, 0);

    for (int i = 1; i < GCN_NUM; i++){
        k_gemm_p<<<(N_POI+127)/128, 512, smem_gemm>>>(
            (const void*)encH, (const float4*)(gcnW + i*DIM*DIM), (uint32_t*)tmpH,
            N_POI, 0);
        k_spmm_f<<<(N_POI+7)/8, 256>>>((const uint2*)tmpH, rowptr, edge, dis,
                                       (const float4*)(gcnb + i*DIM),
                                       (uint2*)encH, (float4*)bA,
                                       (i == GCN_NUM-1) ? 1 : 0);
    }
    const float* encF = bA;

    // attention
    k_qkv_h<<<dim3(NTOK/128, 3), 512, smem_gemm>>>((const uint2*)encH, xidx,
                                                   (const float4*)inw, inb, qkv);
    k_attn<<<dim3(BATCH, 8), 128, smem_attn>>>(qkv, obuf);
    k_tail<<<BATCH, 128>>>(obuf, ow, ob, encF, pidx, out);
}